// round 13
// baseline (speedup 1.0000x reference)
#include <cuda_runtime.h>
#include <cuda_fp16.h>
#include <cstdint>
#include <cstddef>

// Problem constants (fixed by the dataset)
#define NR    16384
#define NCH   65536
#define NP    16384
#define DIM   64
#define ERC   65536
#define EPASS 65536
#define VT    128    // channel rows per fused-kernel block (2 x 64-row halves)

// Device scratch (allocation-free rule: __device__ globals)
__device__ float  g_s   [(size_t)NCH * DIM];  // 16 MB: sum of h_packet per channel
__device__ float  g_cnt [NCH];                // edge count per channel
__device__ float  g_hin [(size_t)NCH * DIM];  // 16 MB
__device__ float  g_hout[(size_t)NCH * DIM];  // 16 MB
__device__ float  g_min [(size_t)NCH * 32];   // 8 MB (dense write, no zero needed)
__device__ float  g_mout[(size_t)NCH * 32];   // 8 MB
__device__ uint4  g_wfrag[32 * 4 * 4 * 32];   // 256 KB: W_p as MMA B-fragments
__device__ float  g_bperm[2048];              // b_p permuted: bperm[k*64+d] = b_p[d*32+k]

// Side stream + fork/join events, created once at load time.
struct SideStream {
    cudaStream_t s2;
    cudaEvent_t evFork, evJoin;
    SideStream() {
        cudaStreamCreate(&s2);
        cudaEventCreateWithFlags(&evFork, cudaEventDisableTiming);
        cudaEventCreateWithFlags(&evJoin, cudaEventDisableTiming);
    }
};
static SideStream g_ss;

__device__ __forceinline__ void red_add_v4(float* p, float4 v) {
    asm volatile("red.global.add.v4.f32 [%0], {%1,%2,%3,%4};"
                 :: "l"(p), "f"(v.x), "f"(v.y), "f"(v.z), "f"(v.w) : "memory");
}
__device__ __forceinline__ void red_add_f(float* p, float v) {
    asm volatile("red.global.add.f32 [%0], %1;" :: "l"(p), "f"(v) : "memory");
}
__device__ __forceinline__ uint32_t smem_u32(const void* p) {
    return (uint32_t)__cvta_generic_to_shared(p);
}
__device__ __forceinline__ uint4 f8_to_h8(float4 lo, float4 hi) {
    __half2 h0 = __floats2half2_rn(lo.x, lo.y);
    __half2 h1 = __floats2half2_rn(lo.z, lo.w);
    __half2 h2 = __floats2half2_rn(hi.x, hi.y);
    __half2 h3 = __floats2half2_rn(hi.z, hi.w);
    return make_uint4(*(unsigned*)&h0, *(unsigned*)&h1,
                      *(unsigned*)&h2, *(unsigned*)&h3);
}

// ---------------------------------------------------------------------------
// K0a (main): zero hin/hout/s/cnt
__global__ void zero_hs_kernel(float4* __restrict__ hin, float4* __restrict__ hout,
                               float4* __restrict__ s, float4* __restrict__ cnt) {
    const int n_h = (NCH * DIM) / 4;
    const int n_c = NCH / 4;
    float4 z = make_float4(0.f, 0.f, 0.f, 0.f);
    int stride = gridDim.x * blockDim.x;
    for (int i = blockIdx.x * blockDim.x + threadIdx.x; i < n_h; i += stride) {
        hin[i] = z; hout[i] = z; s[i] = z;
    }
    for (int i = blockIdx.x * blockDim.x + threadIdx.x; i < n_c; i += stride) cnt[i] = z;
}
// K0b (side): zero out
__global__ void zero_out_kernel(float4* __restrict__ out) {
    int i = blockIdx.x * blockDim.x + threadIdx.x;
    out[i] = make_float4(0.f, 0.f, 0.f, 0.f);
}

// ---------------------------------------------------------------------------
// K1: all three scatters in one launch; 8 threads per edge, 2 float4 chunks
// per thread (more ILP per thread than the 16-thread version).
__global__ void mega_scatter_kernel(
        const int* __restrict__ src0, const int* __restrict__ dst0,
        const int* __restrict__ src1, const int* __restrict__ dst1,
        const int* __restrict__ src2, const int* __restrict__ dst2,
        const float* __restrict__ h_router, const float* __restrict__ h_packet,
        float* __restrict__ hin, float* __restrict__ hout,
        float* __restrict__ s, float* __restrict__ cnt) {
    int tid = blockIdx.x * blockDim.x + threadIdx.x;
    int e = tid >> 3;
    int c = tid & 7;
    const int* src; const int* dst; const float* h; float* acc;
    bool do_cnt = false;
    if (e < ERC)          { src = src0; dst = dst0; h = h_router; acc = hin; }
    else if (e < 2 * ERC) { e -= ERC; src = src1; dst = dst1; h = h_router; acc = hout; }
    else if (e < 3 * ERC) { e -= 2 * ERC; src = src2; dst = dst2; h = h_packet; acc = s;
                            do_cnt = (c == 0); }
    else return;
    int sidx = src[e];
    int d = dst[e];
    float4 v0 = *(const float4*)(h + (size_t)sidx * DIM + c * 4);
    float4 v1 = *(const float4*)(h + (size_t)sidx * DIM + (c + 8) * 4);
    red_add_v4(acc + (size_t)d * DIM + c * 4, v0);
    red_add_v4(acc + (size_t)d * DIM + (c + 8) * 4, v1);
    if (do_cnt) red_add_f(cnt + d, 1.0f);
}

// ---------------------------------------------------------------------------
// K2a (side): extract W_p into MMA B-fragment order (one warp per k).
// Layout: g_wfrag[((k*4 + ks)*4 + nb)*32 + lane] = {bf0,bf1,bf2,bf3}.
__global__ void __launch_bounds__(128) prep_w_frag(
        const float* __restrict__ Wp, uint4* __restrict__ wfrag) {
    __shared__ __align__(16) __half Wsm[4][64 * 64];   // 32 KB
    const int t = threadIdx.x, wid = t >> 5, lane = t & 31;
    const int k = blockIdx.x * 4 + wid;
    __half* W = Wsm[wid];
#pragma unroll
    for (int i = 0; i < 16; i++) {
        int idx = i * 32 + lane;         // 0..511
        int d = idx >> 3, ch = idx & 7;
        const float4* gp = (const float4*)(Wp + (size_t)(d * 32 + k) * DIM + ch * 8);
        *(uint4*)(W + (d << 6) + ((ch ^ (d & 7)) << 3)) = f8_to_h8(gp[0], gp[1]);
    }
    __syncwarp();
#pragma unroll
    for (int ks = 0; ks < 4; ks++) {
        const int lrow = lane & 15;
        const int lch  = 2 * ks + (lane >> 4);
#pragma unroll
        for (int nb = 0; nb < 4; nb++) {
            int r = nb * 16 + lrow;
            uint32_t addr = smem_u32(W + r * 64 + (lch ^ (r & 7)) * 8);
            uint32_t b0, b1, b2, b3;
            asm volatile("ldmatrix.sync.aligned.m8n8.x4.shared.b16 {%0,%1,%2,%3}, [%4];"
                : "=r"(b0), "=r"(b1), "=r"(b2), "=r"(b3) : "r"(addr));
            wfrag[((k * 4 + ks) * 4 + nb) * 32 + lane] = make_uint4(b0, b1, b2, b3);
        }
    }
}
// K2b (side): permute b_p
__global__ void prep_bias(const float* __restrict__ bp, float* __restrict__ bperm) {
    int i = blockIdx.x * blockDim.x + threadIdx.x;   // 2048 threads
    int k = i >> 6, d = i & 63;
    bperm[i] = bp[d * 32 + k];
}

// ---------------------------------------------------------------------------
// K3: fused bilinear. Block covers 128 channel rows processed as TWO
// sequential 64-row halves (mt=0,1); 128 threads, 4 warps x 16 rows per half
// -> each warp covers 32 rows total, halving W-fragment LDS per row.
// W fragments stream through a 2x16KB smem ring (2 k per chunk, 32 phases:
// 16 chunks per half, ring traversed twice). 74.75 KB smem -> 3 blocks/SM.
#define FB_W     0          // 2 x 16384 (double-buffered W chunks, 2 k each)
#define FB_S     32768      // 16384: S tile (128 rows) fp16 swizzled
#define FB_BP    49152      // 8192: bias perm f32
#define FB_MIN   57344      // 8448: [64][33] f32 (reused per half)
#define FB_MOUT  65792      // 8448
#define FB_CNT   74240      // 512
#define FB_TOTAL 74752

__global__ void __launch_bounds__(128, 3) fused_bilinear(
        const float* __restrict__ s, const float* __restrict__ cnt,
        const float* __restrict__ hin, const float* __restrict__ hout,
        const uint4* __restrict__ wfrag, const float* __restrict__ bperm,
        float* __restrict__ min_, float* __restrict__ mout_) {
    extern __shared__ __align__(16) char sm[];
    uint4*  Wbuf = (uint4*)(sm + FB_W);
    __half* Ssm  = (__half*)(sm + FB_S);
    float*  BPs  = (float*)(sm + FB_BP);
    float*  Min  = (float*)(sm + FB_MIN);
    float*  Mout = (float*)(sm + FB_MOUT);
    float*  CNTs = (float*)(sm + FB_CNT);

    const int t = threadIdx.x, wid = t >> 5, lane = t & 31;
    const int vt0 = blockIdx.x * VT;

    // prefetch phase-0 W chunk (k=0,1): 16 KB = 1024 uint4, 8 per thread
#pragma unroll
    for (int i = 0; i < 8; i++) {
        int idx = i * 128 + t;
        uint32_t dsm = smem_u32(Wbuf + idx);
        asm volatile("cp.async.ca.shared.global [%0], [%1], 16;"
                     :: "r"(dsm), "l"(wfrag + idx));
    }
    asm volatile("cp.async.commit_group;");

    // S tile: 128 rows x 64 fp16, swizzled (1024 16B-chunks, 8 per thread)
#pragma unroll
    for (int i = 0; i < 8; i++) {
        int idx = i * 128 + t;
        int r = idx >> 3, ch = idx & 7;
        const float4* gp = (const float4*)(s + (size_t)(vt0 + r) * DIM + ch * 8);
        *(uint4*)(Ssm + r * 64 + ((ch ^ (r & 7)) << 3)) = f8_to_h8(gp[0], gp[1]);
    }
    for (int i = t; i < 512; i += 128)
        ((float4*)BPs)[i] = ((const float4*)bperm)[i];
    CNTs[t] = cnt[vt0 + t];
    __syncthreads();

    const int vbase = wid * 16;
    const int tr0 = vbase + (lane >> 2);   // row within the 64-row half
    const int tr1 = tr0 + 8;
    const int dq = 2 * (lane & 3);

    uint32_t a[4][4];
    float2 hi0[8], hi1[8], ho0[8], ho1[8];
    float cnt0 = 0.f, cnt1 = 0.f;

    for (int p = 0; p < 32; p++) {
        const int mt = p >> 4;
        if ((p & 15) == 0) {
            if (p == 16) {
                // writeback half 0, then reuse Min/Mout for half 1
                __syncthreads();
                for (int i = t; i < 512; i += 128) {
                    int r = i >> 3, c = (i & 7) * 4;
                    float4 vi = make_float4(Min[r * 33 + c], Min[r * 33 + c + 1],
                                            Min[r * 33 + c + 2], Min[r * 33 + c + 3]);
                    float4 vo = make_float4(Mout[r * 33 + c], Mout[r * 33 + c + 1],
                                            Mout[r * 33 + c + 2], Mout[r * 33 + c + 3]);
                    *(float4*)(min_  + (size_t)(vt0 + r) * 32 + c) = vi;
                    *(float4*)(mout_ + (size_t)(vt0 + r) * 32 + c) = vo;
                }
                __syncthreads();
            }
            const int rbase = mt * 64;
            // A fragments for this half (k-invariant)
#pragma unroll
            for (int ks = 0; ks < 4; ks++) {
                int lch = 2 * ks + (lane >> 4);
                int r = rbase + vbase + (lane & 15);
                uint32_t addr = smem_u32(Ssm + r * 64 + ((lch ^ (r & 7)) << 3));
                asm volatile("ldmatrix.sync.aligned.m8n8.x4.shared.b16 {%0,%1,%2,%3}, [%4];"
                    : "=r"(a[ks][0]), "=r"(a[ks][1]), "=r"(a[ks][2]), "=r"(a[ks][3])
                    : "r"(addr));
            }
            // h registers for this half (k-invariant)
            const size_t row0 = (size_t)(vt0 + rbase + tr0) * DIM;
            const size_t row1 = (size_t)(vt0 + rbase + tr1) * DIM;
#pragma unroll
            for (int n8 = 0; n8 < 8; n8++) {
                int d0 = n8 * 8 + dq;
                hi0[n8] = *(const float2*)(hin + row0 + d0);
                hi1[n8] = *(const float2*)(hin + row1 + d0);
                ho0[n8] = *(const float2*)(hout + row0 + d0);
                ho1[n8] = *(const float2*)(hout + row1 + d0);
            }
            cnt0 = CNTs[rbase + tr0];
            cnt1 = CNTs[rbase + tr1];
        }

        asm volatile("cp.async.wait_group 0;");
        __syncthreads();   // chunk ready AND all warps past prior use of buffer
        const uint4* Wc = Wbuf + (p & 1) * 1024;
        if (p < 31) {
            const int nc = (p + 1) & 15;
            const uint4* gsrc = wfrag + nc * 1024;
            uint4* dbuf = Wbuf + ((p + 1) & 1) * 1024;
#pragma unroll
            for (int i = 0; i < 8; i++) {
                int idx = i * 128 + t;
                uint32_t dsm = smem_u32(dbuf + idx);
                asm volatile("cp.async.ca.shared.global [%0], [%1], 16;"
                             :: "r"(dsm), "l"(gsrc + idx));
            }
            asm volatile("cp.async.commit_group;");
        }

#pragma unroll
        for (int kk = 0; kk < 2; kk++) {
            const int k = (p & 15) * 2 + kk;
            float pacc[8][4];
#pragma unroll
            for (int n8 = 0; n8 < 8; n8++)
#pragma unroll
                for (int j = 0; j < 4; j++) pacc[n8][j] = 0.f;

            const uint4* wf = Wc + kk * 512 + lane;
#pragma unroll
            for (int ks = 0; ks < 4; ks++) {
                uint4 bf[4];
#pragma unroll
                for (int nb = 0; nb < 4; nb++) bf[nb] = wf[(ks * 4 + nb) * 32];
#pragma unroll
                for (int n8 = 0; n8 < 8; n8++) {
                    uint32_t b0 = (n8 & 1) ? bf[n8 >> 1].y : bf[n8 >> 1].x;
                    uint32_t b1 = (n8 & 1) ? bf[n8 >> 1].w : bf[n8 >> 1].z;
                    asm volatile(
                        "mma.sync.aligned.m16n8k16.row.col.f32.f16.f16.f32 "
                        "{%0,%1,%2,%3}, {%4,%5,%6,%7}, {%8,%9}, {%0,%1,%2,%3};"
                        : "+f"(pacc[n8][0]), "+f"(pacc[n8][1]),
                          "+f"(pacc[n8][2]), "+f"(pacc[n8][3])
                        : "r"(a[ks][0]), "r"(a[ks][1]), "r"(a[ks][2]), "r"(a[ks][3]),
                          "r"(b0), "r"(b1));
                }
            }

            float pin0 = 0.f, pin1 = 0.f, po0 = 0.f, po1 = 0.f;
            const float* bpk = BPs + k * 64;
#pragma unroll
            for (int n8 = 0; n8 < 8; n8++) {
                float2 bp2 = *(const float2*)(bpk + n8 * 8 + dq);
                float p00 = pacc[n8][0] + cnt0 * bp2.x;
                float p01 = pacc[n8][1] + cnt0 * bp2.y;
                float p10 = pacc[n8][2] + cnt1 * bp2.x;
                float p11 = pacc[n8][3] + cnt1 * bp2.y;
                pin0 += p00 * hi0[n8].x + p01 * hi0[n8].y;
                pin1 += p10 * hi1[n8].x + p11 * hi1[n8].y;
                po0  += p00 * ho0[n8].x + p01 * ho0[n8].y;
                po1  += p10 * ho1[n8].x + p11 * ho1[n8].y;
            }
            pin0 += __shfl_xor_sync(0xffffffffu, pin0, 1);
            pin0 += __shfl_xor_sync(0xffffffffu, pin0, 2);
            pin1 += __shfl_xor_sync(0xffffffffu, pin1, 1);
            pin1 += __shfl_xor_sync(0xffffffffu, pin1, 2);
            po0  += __shfl_xor_sync(0xffffffffu, po0, 1);
            po0  += __shfl_xor_sync(0xffffffffu, po0, 2);
            po1  += __shfl_xor_sync(0xffffffffu, po1, 1);
            po1  += __shfl_xor_sync(0xffffffffu, po1, 2);
            if ((lane & 3) == 0) {
                Min [tr0 * 33 + k] = pin0;
                Min [tr1 * 33 + k] = pin1;
                Mout[tr0 * 33 + k] = po0;
                Mout[tr1 * 33 + k] = po1;
            }
        }
    }
    __syncthreads();
    // writeback half 1
    for (int i = t; i < 512; i += 128) {
        int r = i >> 3, c = (i & 7) * 4;
        float4 vi = make_float4(Min[r * 33 + c], Min[r * 33 + c + 1],
                                Min[r * 33 + c + 2], Min[r * 33 + c + 3]);
        float4 vo = make_float4(Mout[r * 33 + c], Mout[r * 33 + c + 1],
                                Mout[r * 33 + c + 2], Mout[r * 33 + c + 3]);
        *(float4*)(min_  + (size_t)(vt0 + 64 + r) * 32 + c) = vi;
        *(float4*)(mout_ + (size_t)(vt0 + 64 + r) * 32 + c) = vo;
    }
}

// ---------------------------------------------------------------------------
// K4: gather channel -> router into d_out. 8 lanes per edge, float4 chunks.
__global__ void gather_kernel(const int* __restrict__ isrc, const int* __restrict__ idst,
                              const int* __restrict__ oisrc, const int* __restrict__ oidst,
                              const float* __restrict__ min_, const float* __restrict__ mout_,
                              float* __restrict__ out) {
    int gtid = blockIdx.x * blockDim.x + threadIdx.x;
    int e = gtid >> 3;
    int c = gtid & 7;
    if (e < ERC) {
        int s = isrc[e], d = idst[e];
        float4 v = *(const float4*)(min_ + (size_t)s * 32 + c * 4);
        red_add_v4(out + (size_t)d * DIM + c * 4, v);
    } else if (e < 2 * ERC) {
        int ee = e - ERC;
        int s = oisrc[ee], d = oidst[ee];
        float4 v = *(const float4*)(mout_ + (size_t)s * 32 + c * 4);
        red_add_v4(out + (size_t)d * DIM + 32 + c * 4, v);
    }
}

// ---------------------------------------------------------------------------
// K5: relu epilogue on out
__global__ void relu_kernel(float4* __restrict__ out) {
    int i = blockIdx.x * blockDim.x + threadIdx.x;
    float4 v = out[i];
    v.x = fmaxf(v.x, 0.f); v.y = fmaxf(v.y, 0.f);
    v.z = fmaxf(v.z, 0.f); v.w = fmaxf(v.w, 0.f);
    out[i] = v;
}

// ===========================================================================
extern "C" void kernel_launch(void* const* d_in, const int* in_sizes, int n_in,
                              void* d_out, int out_size) {
    const float* h_router       = (const float*)d_in[0];
    const float* h_packet       = (const float*)d_in[1];
    const float* W_p            = (const float*)d_in[2];
    const float* b_p            = (const float*)d_in[3];
    // d_in[4] = W_c, d_in[5] = b_c : dead code in reference
    const int* output_src       = (const int*)d_in[6];
    const int* output_dst       = (const int*)d_in[7];
    const int* input_inv_src    = (const int*)d_in[8];
    const int* input_inv_dst    = (const int*)d_in[9];
    const int* pass_src         = (const int*)d_in[10];
    const int* pass_dst         = (const int*)d_in[11];
    const int* input_src        = (const int*)d_in[12];
    const int* input_dst        = (const int*)d_in[13];
    const int* output_inv_src   = (const int*)d_in[14];
    const int* output_inv_dst   = (const int*)d_in[15];
    float* out = (float*)d_out;

    float *p_s, *p_cnt, *p_hin, *p_hout, *p_min, *p_mout, *p_bperm;
    uint4* p_wfrag;
    cudaGetSymbolAddress((void**)&p_s,     g_s);
    cudaGetSymbolAddress((void**)&p_cnt,   g_cnt);
    cudaGetSymbolAddress((void**)&p_hin,   g_hin);
    cudaGetSymbolAddress((void**)&p_hout,  g_hout);
    cudaGetSymbolAddress((void**)&p_min,   g_min);
    cudaGetSymbolAddress((void**)&p_mout,  g_mout);
    cudaGetSymbolAddress((void**)&p_wfrag, g_wfrag);
    cudaGetSymbolAddress((void**)&p_bperm, g_bperm);

    cudaFuncSetAttribute(fused_bilinear,
                         cudaFuncAttributeMaxDynamicSharedMemorySize, FB_TOTAL);

    // Fork: side stream preps W fragments + bias permutation, zeroes out.
    cudaEventRecord(g_ss.evFork, 0);
    cudaStreamWaitEvent(g_ss.s2, g_ss.evFork, 0);
    prep_w_frag<<<8, 128, 0, g_ss.s2>>>(W_p, p_wfrag);
    prep_bias<<<8, 256, 0, g_ss.s2>>>(b_p, p_bperm);
    zero_out_kernel<<<(NR * DIM) / (4 * 256), 256, 0, g_ss.s2>>>((float4*)out);
    cudaEventRecord(g_ss.evJoin, g_ss.s2);

    // Main: zero accumulators, then all three scatters in one launch
    zero_hs_kernel<<<4096, 256>>>((float4*)p_hin, (float4*)p_hout,
                                  (float4*)p_s, (float4*)p_cnt);
    mega_scatter_kernel<<<(3 * ERC * 8) / 256, 256>>>(
        output_src, output_dst, input_inv_src, input_inv_dst,
        pass_src, pass_dst, h_router, h_packet,
        p_hin, p_hout, p_s, p_cnt);

    // Join, then fused bilinear (needs scatters + prep)
    cudaStreamWaitEvent(0, g_ss.evJoin, 0);
    fused_bilinear<<<NCH / VT, 128, FB_TOTAL>>>(p_s, p_cnt, p_hin, p_hout,
                                                p_wfrag, p_bperm, p_min, p_mout);

    // channel -> router gathers into out
    gather_kernel<<<(2 * ERC * 8) / 256, 256>>>(input_src, input_dst,
                                                output_inv_src, output_inv_dst,
                                                p_min, p_mout, out);

    // relu epilogue
    relu_kernel<<<(NR * DIM) / (4 * 256), 256>>>((float4*)out);
}

// round 14
// speedup vs baseline: 1.3049x; 1.3049x over previous
#include <cuda_runtime.h>
#include <cuda_fp16.h>
#include <cstdint>
#include <cstddef>

// Problem constants (fixed by the dataset)
#define NR    16384
#define NCH   65536
#define NP    16384
#define DIM   64
#define ERC   65536
#define EPASS 65536
#define EN    2048   // D*D/2

// Device scratch (allocation-free rule: __device__ globals)
// g_e TILED layout: addr(u,k,d) = u*2048 + (d>>3)*256 + k*8 + (d&7)
//   -> lane k's chunk c (d in [8c,8c+8)) is the float4 at (u*256 + c*32 + k)
__device__ __half g_e  [(size_t)NP  * EN];   // 64 MB
__device__ float g_hin [(size_t)NCH * DIM];  // 16 MB
__device__ float g_hout[(size_t)NCH * DIM];  // 16 MB
__device__ float g_min [(size_t)NCH * 32];   // 8 MB
__device__ float g_mout[(size_t)NCH * 32];   // 8 MB

// Side stream + fork/join events, created once at load time.
struct SideStream {
    cudaStream_t s2;
    cudaEvent_t evFork, evJoin;
    SideStream() {
        cudaStreamCreate(&s2);
        cudaEventCreateWithFlags(&evFork, cudaEventDisableTiming);
        cudaEventCreateWithFlags(&evJoin, cudaEventDisableTiming);
    }
};
static SideStream g_ss;

__device__ __forceinline__ void red_add_v4(float* p, float4 v) {
    asm volatile("red.global.add.v4.f32 [%0], {%1,%2,%3,%4};"
                 :: "l"(p), "f"(v.x), "f"(v.y), "f"(v.z), "f"(v.w) : "memory");
}
__device__ __forceinline__ void red_add_f(float* p, float v) {
    asm volatile("red.global.add.f32 [%0], %1;" :: "l"(p), "f"(v) : "memory");
}
__device__ __forceinline__ uint32_t smem_u32(const void* p) {
    return (uint32_t)__cvta_generic_to_shared(p);
}

// Map a storage column n (0..2047) to its W_p row: n = c*256 + k*8 + dd,
// d = 8c + dd, W_p row = d*32 + k.
__device__ __forceinline__ int wp_row_of_col(int n) {
    int dd = n & 7;
    int k  = (n >> 3) & 31;
    int c  = n >> 8;
    return (8 * c + dd) * 32 + k;
}

// ---------------------------------------------------------------------------
// K0 (main): zero hin/hout/min/mout/out in one grid-stride launch
__global__ void zero_all_kernel(float4* __restrict__ hin, float4* __restrict__ hout,
                                float4* __restrict__ min_, float4* __restrict__ mout_,
                                float4* __restrict__ out) {
    const int n_h = (NCH * DIM) / 4;
    const int n_m = (NCH * 32) / 4;
    const int n_o = (NR * DIM) / 4;
    float4 z = make_float4(0.f, 0.f, 0.f, 0.f);
    int stride = gridDim.x * blockDim.x;
    for (int i = blockIdx.x * blockDim.x + threadIdx.x; i < n_h; i += stride) {
        hin[i] = z; hout[i] = z;
    }
    for (int i = blockIdx.x * blockDim.x + threadIdx.x; i < n_m; i += stride) {
        min_[i] = z; mout_[i] = z;
    }
    for (int i = blockIdx.x * blockDim.x + threadIdx.x; i < n_o; i += stride) {
        out[i] = z;
    }
}

// ---------------------------------------------------------------------------
// K1: scatter-add h rows along edges: acc[dst[e]] += h[src[e]]  (64 floats/row)
__global__ void scatter_h_kernel(const int* __restrict__ src0, const int* __restrict__ dst0,
                                 const int* __restrict__ src1, const int* __restrict__ dst1,
                                 const float* __restrict__ h,
                                 float* __restrict__ acc0, float* __restrict__ acc1) {
    int tid = blockIdx.x * blockDim.x + threadIdx.x;
    int e = tid >> 4;
    int c = tid & 15;
    const int* src; const int* dst; float* acc;
    if (e < ERC) { src = src0; dst = dst0; acc = acc0; }
    else if (e < 2 * ERC) { e -= ERC; src = src1; dst = dst1; acc = acc1; }
    else return;
    int s = src[e];
    int d = dst[e];
    float4 v = *(const float4*)(h + (size_t)s * DIM + c * 4);
    red_add_v4(acc + (size_t)d * DIM + c * 4, v);
}

// ---------------------------------------------------------------------------
// K2: e = h_packet @ W_p^T + b_p  -> TILED fp16 output (see g_e comment).
// Storage col n reads W_p row wp_row_of_col(n). HMMA m16n8k16, fp32 acc,
// 128x128 tile, 8 warps (2m x 4n), K=64 in 4 k-steps, single stage.
__global__ void __launch_bounds__(256) gemm_e_hmma(
        const float* __restrict__ A,    // [NP, 64] h_packet
        const float* __restrict__ B,    // [2048, 64] W_p
        const float* __restrict__ bias, // [2048] b_p
        __half* __restrict__ C) {       // [NP, 2048] tiled
    __shared__ __align__(16) __half As[128 * 64];
    __shared__ __align__(16) __half Bs[128 * 64];
    const int t  = threadIdx.x;
    const int m0 = blockIdx.y * 128;
    const int n0 = blockIdx.x * 128;

    {
        const float* G0 = A + (size_t)m0 * DIM;
#pragma unroll
        for (int i = 0; i < 4; i++) {
            int idx = i * 256 + t;      // 0..1023
            int r = idx >> 3, ch = idx & 7;
            int pch = ch ^ (r & 7);
            {
                const float4* gp = (const float4*)(G0 + (size_t)r * DIM + ch * 8);
                float4 lo = gp[0], hi = gp[1];
                __half2 h0 = __floats2half2_rn(lo.x, lo.y);
                __half2 h1 = __floats2half2_rn(lo.z, lo.w);
                __half2 h2 = __floats2half2_rn(hi.x, hi.y);
                __half2 h3 = __floats2half2_rn(hi.z, hi.w);
                uint4 v = make_uint4(*(unsigned*)&h0, *(unsigned*)&h1,
                                     *(unsigned*)&h2, *(unsigned*)&h3);
                *(uint4*)(As + r * 64 + pch * 8) = v;
            }
            {
                int brow = wp_row_of_col(n0 + r);   // permuted W_p row
                const float4* gp = (const float4*)(B + (size_t)brow * DIM + ch * 8);
                float4 lo = gp[0], hi = gp[1];
                __half2 h0 = __floats2half2_rn(lo.x, lo.y);
                __half2 h1 = __floats2half2_rn(lo.z, lo.w);
                __half2 h2 = __floats2half2_rn(hi.x, hi.y);
                __half2 h3 = __floats2half2_rn(hi.z, hi.w);
                uint4 v = make_uint4(*(unsigned*)&h0, *(unsigned*)&h1,
                                     *(unsigned*)&h2, *(unsigned*)&h3);
                *(uint4*)(Bs + r * 64 + pch * 8) = v;
            }
        }
    }
    __syncthreads();

    const int wid  = t >> 5, lane = t & 31;
    const int mbase = (wid >> 2) * 64;   // warp_m in {0,1}
    const int nbase = (wid & 3) * 32;    // warp_n in {0..3}

    float acc[4][4][4];
#pragma unroll
    for (int mt = 0; mt < 4; mt++)
#pragma unroll
        for (int nt = 0; nt < 4; nt++)
#pragma unroll
            for (int j = 0; j < 4; j++) acc[mt][nt][j] = 0.f;

#pragma unroll
    for (int ks = 0; ks < 4; ks++) {
        uint32_t a[4][4], bf[2][4];
        const int lrow = lane & 15;
        const int lch  = 2 * ks + (lane >> 4);
#pragma unroll
        for (int mt = 0; mt < 4; mt++) {
            int r = mbase + mt * 16 + lrow;
            uint32_t addr = smem_u32(As + r * 64 + (lch ^ (r & 7)) * 8);
            asm volatile("ldmatrix.sync.aligned.m8n8.x4.shared.b16 {%0,%1,%2,%3}, [%4];"
                : "=r"(a[mt][0]), "=r"(a[mt][1]), "=r"(a[mt][2]), "=r"(a[mt][3])
                : "r"(addr));
        }
#pragma unroll
        for (int np = 0; np < 2; np++) {
            int r = nbase + np * 16 + lrow;
            uint32_t addr = smem_u32(Bs + r * 64 + (lch ^ (r & 7)) * 8);
            asm volatile("ldmatrix.sync.aligned.m8n8.x4.shared.b16 {%0,%1,%2,%3}, [%4];"
                : "=r"(bf[np][0]), "=r"(bf[np][1]), "=r"(bf[np][2]), "=r"(bf[np][3])
                : "r"(addr));
        }
#pragma unroll
        for (int mt = 0; mt < 4; mt++)
#pragma unroll
            for (int nt = 0; nt < 4; nt++) {
                uint32_t b0 = bf[nt >> 1][nt & 1];
                uint32_t b1 = bf[nt >> 1][2 + (nt & 1)];
                asm volatile(
                    "mma.sync.aligned.m16n8k16.row.col.f32.f16.f16.f32 "
                    "{%0,%1,%2,%3}, {%4,%5,%6,%7}, {%8,%9}, {%0,%1,%2,%3};"
                    : "+f"(acc[mt][nt][0]), "+f"(acc[mt][nt][1]),
                      "+f"(acc[mt][nt][2]), "+f"(acc[mt][nt][3])
                    : "r"(a[mt][0]), "r"(a[mt][1]), "r"(a[mt][2]), "r"(a[mt][3]),
                      "r"(b0), "r"(b1));
            }
    }

    const int row_l = lane >> 2;
    const int col_l = (lane & 3) * 2;
#pragma unroll
    for (int mt = 0; mt < 4; mt++) {
        int m = m0 + mbase + mt * 16 + row_l;
#pragma unroll
        for (int nt = 0; nt < 4; nt++) {
            int n = n0 + nbase + nt * 8 + col_l;   // even, n&7 <= 6
            int b0row = wp_row_of_col(n);
            float bx = bias[b0row];
            float by = bias[b0row + 32];           // col n+1: d+1 -> row+32
            __half2 h01 = __floats2half2_rn(acc[mt][nt][0] + bx,
                                            acc[mt][nt][1] + by);
            __half2 h23 = __floats2half2_rn(acc[mt][nt][2] + bx,
                                            acc[mt][nt][3] + by);
            *(__half2*)(C + (size_t)m * EN + n)       = h01;
            *(__half2*)(C + (size_t)(m + 8) * EN + n) = h23;
        }
    }
}

// ---------------------------------------------------------------------------
// K3: pass edges, tiled e. One warp per edge; lane = k (0..31):
//   m_in[v,k]  = sum_d e[u,k,d] * h_in[v,d]   (same for m_out)
// All 8 coalesced LDG.128 issued upfront (MLP=8), then HFMA2 chunk
// accumulation with packed-half2 shfl broadcast of h. No cross-lane reduce.
__global__ void pass_kernel(
        const int* __restrict__ psrc, const int* __restrict__ pdst,
        const __half* __restrict__ ek,
        const float* __restrict__ hin, const float* __restrict__ hout,
        float* __restrict__ min_, float* __restrict__ mout_) {
    int gtid = blockIdx.x * blockDim.x + threadIdx.x;
    int w    = gtid >> 5;
    int lane = gtid & 31;
    if (w >= EPASS) return;
    int u = psrc[w];
    int v = pdst[w];

    const float4* ev4 = (const float4*)(ek + (size_t)u * EN) + lane;

    // batch all e loads (8 independent LDG.128, coalesced across lanes)
    float4 ev[8];
#pragma unroll
    for (int c = 0; c < 8; c++) ev[c] = ev4[c * 32];

    // packed h: lane j holds (h[2j], h[2j+1]) as half2
    float2 fi = *(const float2*)(hin  + (size_t)v * DIM + 2 * lane);
    float2 fo = *(const float2*)(hout + (size_t)v * DIM + 2 * lane);
    __half2 phi = __floats2half2_rn(fi.x, fi.y);
    __half2 pho = __floats2half2_rn(fo.x, fo.y);
    unsigned phiu = *(unsigned*)&phi;
    unsigned phou = *(unsigned*)&pho;

    float mi = 0.f, mo = 0.f;
#pragma unroll
    for (int c = 0; c < 8; c++) {               // d chunk = [8c, 8c+8)
        const __half2* ep = (const __half2*)&ev[c];  // 4 half2: d pairs
        __half2 acci, acco;
#pragma unroll
        for (int tt = 0; tt < 4; tt++) {
            unsigned hiu = __shfl_sync(0xffffffffu, phiu, 4 * c + tt);
            unsigned hou = __shfl_sync(0xffffffffu, phou, 4 * c + tt);
            __half2 hih = *(__half2*)&hiu;
            __half2 hoh = *(__half2*)&hou;
            if (tt == 0) { acci = __hmul2(ep[0], hih); acco = __hmul2(ep[0], hoh); }
            else         { acci = __hfma2(ep[tt], hih, acci);
                           acco = __hfma2(ep[tt], hoh, acco); }
        }
        float2 ai = __half22float2(acci);
        float2 ao = __half22float2(acco);
        mi += ai.x + ai.y;
        mo += ao.x + ao.y;
    }

    red_add_f(min_  + (size_t)v * 32 + lane, mi);
    red_add_f(mout_ + (size_t)v * 32 + lane, mo);
}

// ---------------------------------------------------------------------------
// K4: gather channel -> router into d_out. 8 lanes per edge, float4 chunks.
__global__ void gather_kernel(const int* __restrict__ isrc, const int* __restrict__ idst,
                              const int* __restrict__ oisrc, const int* __restrict__ oidst,
                              const float* __restrict__ min_, const float* __restrict__ mout_,
                              float* __restrict__ out) {
    int gtid = blockIdx.x * blockDim.x + threadIdx.x;
    int e = gtid >> 3;
    int c = gtid & 7;
    if (e < ERC) {
        int s = isrc[e], d = idst[e];
        float4 v = *(const float4*)(min_ + (size_t)s * 32 + c * 4);
        red_add_v4(out + (size_t)d * DIM + c * 4, v);
    } else if (e < 2 * ERC) {
        int ee = e - ERC;
        int s = oisrc[ee], d = oidst[ee];
        float4 v = *(const float4*)(mout_ + (size_t)s * 32 + c * 4);
        red_add_v4(out + (size_t)d * DIM + 32 + c * 4, v);
    }
}

// ---------------------------------------------------------------------------
// K5: relu epilogue on out
__global__ void relu_kernel(float4* __restrict__ out) {
    int i = blockIdx.x * blockDim.x + threadIdx.x;
    float4 v = out[i];
    v.x = fmaxf(v.x, 0.f); v.y = fmaxf(v.y, 0.f);
    v.z = fmaxf(v.z, 0.f); v.w = fmaxf(v.w, 0.f);
    out[i] = v;
}

// ===========================================================================
extern "C" void kernel_launch(void* const* d_in, const int* in_sizes, int n_in,
                              void* d_out, int out_size) {
    const float* h_router       = (const float*)d_in[0];
    const float* h_packet       = (const float*)d_in[1];
    const float* W_p            = (const float*)d_in[2];
    const float* b_p            = (const float*)d_in[3];
    // d_in[4] = W_c, d_in[5] = b_c : dead code in reference
    const int* output_src       = (const int*)d_in[6];
    const int* output_dst       = (const int*)d_in[7];
    const int* input_inv_src    = (const int*)d_in[8];
    const int* input_inv_dst    = (const int*)d_in[9];
    const int* pass_src         = (const int*)d_in[10];
    const int* pass_dst         = (const int*)d_in[11];
    const int* input_src        = (const int*)d_in[12];
    const int* input_dst        = (const int*)d_in[13];
    const int* output_inv_src   = (const int*)d_in[14];
    const int* output_inv_dst   = (const int*)d_in[15];
    float* out = (float*)d_out;

    __half* p_e;
    float *p_hin, *p_hout, *p_min, *p_mout;
    cudaGetSymbolAddress((void**)&p_e,    g_e);
    cudaGetSymbolAddress((void**)&p_hin,  g_hin);
    cudaGetSymbolAddress((void**)&p_hout, g_hout);
    cudaGetSymbolAddress((void**)&p_min,  g_min);
    cudaGetSymbolAddress((void**)&p_mout, g_mout);

    // Fork: side stream runs ONLY the GEMM (starts immediately, fully
    // overlapped with the zero + scatter chain on the main stream).
    cudaEventRecord(g_ss.evFork, 0);
    cudaStreamWaitEvent(g_ss.s2, g_ss.evFork, 0);
    {
        dim3 grid(EN / 128, NP / 128);  // (16, 128)
        gemm_e_hmma<<<grid, 256, 0, g_ss.s2>>>(h_packet, W_p, b_p, p_e);
    }
    cudaEventRecord(g_ss.evJoin, g_ss.s2);

    // Main stream: zero everything, then router->channel scatters
    zero_all_kernel<<<2048, 256>>>((float4*)p_hin, (float4*)p_hout,
                                   (float4*)p_min, (float4*)p_mout, (float4*)out);
    scatter_h_kernel<<<(2 * ERC * 16) / 256, 256>>>(
        output_src, output_dst, input_inv_src, input_inv_dst,
        h_router, p_hin, p_hout);

    // Join: pass needs the GEMM output, zeroed m buffers, and scattered h
    cudaStreamWaitEvent(0, g_ss.evJoin, 0);

    // pass edges: warp per edge, lane = k
    pass_kernel<<<(EPASS * 32) / 256, 256>>>(pass_src, pass_dst, p_e,
                                             p_hin, p_hout, p_min, p_mout);

    // channel -> router gathers into out (8 lanes/edge, vectorized)
    gather_kernel<<<(2 * ERC * 8) / 256, 256>>>(input_src, input_dst,
                                                output_inv_src, output_inv_dst,
                                                p_min, p_mout, out);

    // relu epilogue
    relu_kernel<<<(NR * DIM) / (4 * 256), 256>>>((float4*)out);
}

// round 15
// speedup vs baseline: 1.3134x; 1.0065x over previous
#include <cuda_runtime.h>
#include <cuda_fp16.h>
#include <cstdint>
#include <cstddef>

// Problem constants (fixed by the dataset)
#define NR    16384
#define NCH   65536
#define NP    16384
#define DIM   64
#define ERC   65536
#define EPASS 65536
#define EN    2048   // D*D/2

// Device scratch (allocation-free rule: __device__ globals)
// g_e TILED layout: addr(u,k,d) = u*2048 + (d>>3)*256 + k*8 + (d&7)
//   -> lane k's chunk c (d in [8c,8c+8)) is the float4 at (u*256 + c*32 + k)
__device__ __half g_e  [(size_t)NP  * EN];   // 64 MB
__device__ float g_hin [(size_t)NCH * DIM];  // 16 MB
__device__ float g_hout[(size_t)NCH * DIM];  // 16 MB
__device__ float g_min [(size_t)NCH * 32];   // 8 MB
__device__ float g_mout[(size_t)NCH * 32];   // 8 MB

// Side stream + fork/join events, created once at load time.
struct SideStream {
    cudaStream_t s2;
    cudaEvent_t evFork, evJoin;
    SideStream() {
        cudaStreamCreate(&s2);
        cudaEventCreateWithFlags(&evFork, cudaEventDisableTiming);
        cudaEventCreateWithFlags(&evJoin, cudaEventDisableTiming);
    }
};
static SideStream g_ss;

__device__ __forceinline__ void red_add_v4(float* p, float4 v) {
    asm volatile("red.global.add.v4.f32 [%0], {%1,%2,%3,%4};"
                 :: "l"(p), "f"(v.x), "f"(v.y), "f"(v.z), "f"(v.w) : "memory");
}
__device__ __forceinline__ void red_add_f(float* p, float v) {
    asm volatile("red.global.add.f32 [%0], %1;" :: "l"(p), "f"(v) : "memory");
}
__device__ __forceinline__ uint32_t smem_u32(const void* p) {
    return (uint32_t)__cvta_generic_to_shared(p);
}

// Map a storage column n (0..2047) to its W_p row: n = c*256 + k*8 + dd,
// d = 8c + dd, W_p row = d*32 + k.
__device__ __forceinline__ int wp_row_of_col(int n) {
    int dd = n & 7;
    int k  = (n >> 3) & 31;
    int c  = n >> 8;
    return (8 * c + dd) * 32 + k;
}

// ---------------------------------------------------------------------------
// K0a (main stream): zero hin/hout
__global__ void zero_h_kernel(float4* __restrict__ hin, float4* __restrict__ hout) {
    const int n_h = (NCH * DIM) / 4;
    float4 z = make_float4(0.f, 0.f, 0.f, 0.f);
    int stride = gridDim.x * blockDim.x;
    for (int i = blockIdx.x * blockDim.x + threadIdx.x; i < n_h; i += stride) {
        hin[i] = z; hout[i] = z;
    }
}
// K0b (side stream): zero min/mout/out
__global__ void zero_m_kernel(float4* __restrict__ min_, float4* __restrict__ mout_,
                              float4* __restrict__ out) {
    const int n_m = (NCH * 32) / 4;
    const int n_o = (NR * DIM) / 4;
    float4 z = make_float4(0.f, 0.f, 0.f, 0.f);
    int stride = gridDim.x * blockDim.x;
    for (int i = blockIdx.x * blockDim.x + threadIdx.x; i < n_m; i += stride) {
        min_[i] = z; mout_[i] = z;
    }
    for (int i = blockIdx.x * blockDim.x + threadIdx.x; i < n_o; i += stride) {
        out[i] = z;
    }
}

// ---------------------------------------------------------------------------
// K1: scatter-add h rows along edges: acc[dst[e]] += h[src[e]]  (64 floats/row)
__global__ void scatter_h_kernel(const int* __restrict__ src0, const int* __restrict__ dst0,
                                 const int* __restrict__ src1, const int* __restrict__ dst1,
                                 const float* __restrict__ h,
                                 float* __restrict__ acc0, float* __restrict__ acc1) {
    int tid = blockIdx.x * blockDim.x + threadIdx.x;
    int e = tid >> 4;
    int c = tid & 15;
    const int* src; const int* dst; float* acc;
    if (e < ERC) { src = src0; dst = dst0; acc = acc0; }
    else if (e < 2 * ERC) { e -= ERC; src = src1; dst = dst1; acc = acc1; }
    else return;
    int s = src[e];
    int d = dst[e];
    float4 v = *(const float4*)(h + (size_t)s * DIM + c * 4);
    red_add_v4(acc + (size_t)d * DIM + c * 4, v);
}

// ---------------------------------------------------------------------------
// K2: e = h_packet @ W_p^T + b_p  -> TILED fp16 output (see g_e comment).
// Storage col n reads W_p row wp_row_of_col(n). HMMA m16n8k16, fp32 acc,
// 128x128 tile, 8 warps (2m x 4n), K=64 in 4 k-steps, single stage.
__global__ void __launch_bounds__(256) gemm_e_hmma(
        const float* __restrict__ A,    // [NP, 64] h_packet
        const float* __restrict__ B,    // [2048, 64] W_p
        const float* __restrict__ bias, // [2048] b_p
        __half* __restrict__ C) {       // [NP, 2048] tiled
    __shared__ __align__(16) __half As[128 * 64];
    __shared__ __align__(16) __half Bs[128 * 64];
    const int t  = threadIdx.x;
    const int m0 = blockIdx.y * 128;
    const int n0 = blockIdx.x * 128;

    {
        const float* G0 = A + (size_t)m0 * DIM;
#pragma unroll
        for (int i = 0; i < 4; i++) {
            int idx = i * 256 + t;      // 0..1023
            int r = idx >> 3, ch = idx & 7;
            int pch = ch ^ (r & 7);
            {
                const float4* gp = (const float4*)(G0 + (size_t)r * DIM + ch * 8);
                float4 lo = gp[0], hi = gp[1];
                __half2 h0 = __floats2half2_rn(lo.x, lo.y);
                __half2 h1 = __floats2half2_rn(lo.z, lo.w);
                __half2 h2 = __floats2half2_rn(hi.x, hi.y);
                __half2 h3 = __floats2half2_rn(hi.z, hi.w);
                uint4 v = make_uint4(*(unsigned*)&h0, *(unsigned*)&h1,
                                     *(unsigned*)&h2, *(unsigned*)&h3);
                *(uint4*)(As + r * 64 + pch * 8) = v;
            }
            {
                int brow = wp_row_of_col(n0 + r);   // permuted W_p row
                const float4* gp = (const float4*)(B + (size_t)brow * DIM + ch * 8);
                float4 lo = gp[0], hi = gp[1];
                __half2 h0 = __floats2half2_rn(lo.x, lo.y);
                __half2 h1 = __floats2half2_rn(lo.z, lo.w);
                __half2 h2 = __floats2half2_rn(hi.x, hi.y);
                __half2 h3 = __floats2half2_rn(hi.z, hi.w);
                uint4 v = make_uint4(*(unsigned*)&h0, *(unsigned*)&h1,
                                     *(unsigned*)&h2, *(unsigned*)&h3);
                *(uint4*)(Bs + r * 64 + pch * 8) = v;
            }
        }
    }
    __syncthreads();

    const int wid  = t >> 5, lane = t & 31;
    const int mbase = (wid >> 2) * 64;   // warp_m in {0,1}
    const int nbase = (wid & 3) * 32;    // warp_n in {0..3}

    float acc[4][4][4];
#pragma unroll
    for (int mt = 0; mt < 4; mt++)
#pragma unroll
        for (int nt = 0; nt < 4; nt++)
#pragma unroll
            for (int j = 0; j < 4; j++) acc[mt][nt][j] = 0.f;

#pragma unroll
    for (int ks = 0; ks < 4; ks++) {
        uint32_t a[4][4], bf[2][4];
        const int lrow = lane & 15;
        const int lch  = 2 * ks + (lane >> 4);
#pragma unroll
        for (int mt = 0; mt < 4; mt++) {
            int r = mbase + mt * 16 + lrow;
            uint32_t addr = smem_u32(As + r * 64 + (lch ^ (r & 7)) * 8);
            asm volatile("ldmatrix.sync.aligned.m8n8.x4.shared.b16 {%0,%1,%2,%3}, [%4];"
                : "=r"(a[mt][0]), "=r"(a[mt][1]), "=r"(a[mt][2]), "=r"(a[mt][3])
                : "r"(addr));
        }
#pragma unroll
        for (int np = 0; np < 2; np++) {
            int r = nbase + np * 16 + lrow;
            uint32_t addr = smem_u32(Bs + r * 64 + (lch ^ (r & 7)) * 8);
            asm volatile("ldmatrix.sync.aligned.m8n8.x4.shared.b16 {%0,%1,%2,%3}, [%4];"
                : "=r"(bf[np][0]), "=r"(bf[np][1]), "=r"(bf[np][2]), "=r"(bf[np][3])
                : "r"(addr));
        }
#pragma unroll
        for (int mt = 0; mt < 4; mt++)
#pragma unroll
            for (int nt = 0; nt < 4; nt++) {
                uint32_t b0 = bf[nt >> 1][nt & 1];
                uint32_t b1 = bf[nt >> 1][2 + (nt & 1)];
                asm volatile(
                    "mma.sync.aligned.m16n8k16.row.col.f32.f16.f16.f32 "
                    "{%0,%1,%2,%3}, {%4,%5,%6,%7}, {%8,%9}, {%0,%1,%2,%3};"
                    : "+f"(acc[mt][nt][0]), "+f"(acc[mt][nt][1]),
                      "+f"(acc[mt][nt][2]), "+f"(acc[mt][nt][3])
                    : "r"(a[mt][0]), "r"(a[mt][1]), "r"(a[mt][2]), "r"(a[mt][3]),
                      "r"(b0), "r"(b1));
            }
    }

    const int row_l = lane >> 2;
    const int col_l = (lane & 3) * 2;
#pragma unroll
    for (int mt = 0; mt < 4; mt++) {
        int m = m0 + mbase + mt * 16 + row_l;
#pragma unroll
        for (int nt = 0; nt < 4; nt++) {
            int n = n0 + nbase + nt * 8 + col_l;   // even, n&7 <= 6
            int b0row = wp_row_of_col(n);
            float bx = bias[b0row];
            float by = bias[b0row + 32];           // col n+1: d+1 -> row+32
            __half2 h01 = __floats2half2_rn(acc[mt][nt][0] + bx,
                                            acc[mt][nt][1] + by);
            __half2 h23 = __floats2half2_rn(acc[mt][nt][2] + bx,
                                            acc[mt][nt][3] + by);
            *(__half2*)(C + (size_t)m * EN + n)       = h01;
            *(__half2*)(C + (size_t)(m + 8) * EN + n) = h23;
        }
    }
}

// ---------------------------------------------------------------------------
// K3: pass edges, tiled e. TWO warps per edge; each warp covers half the
// d-range (32 d values = 4 chunks), lane = k (0..31):
//   m_in[v,k] += sum_{d in half} e[u,k,d] * h_in[v,d]   (same for m_out)
// Both warps red.add partial sums to the same m[v,k]. Halves the per-warp
// dependency chain and register load vs 1 warp/edge; same total chip work.
__global__ void pass_kernel(
        const int* __restrict__ psrc, const int* __restrict__ pdst,
        const __half* __restrict__ ek,
        const float* __restrict__ hin, const float* __restrict__ hout,
        float* __restrict__ min_, float* __restrict__ mout_) {
    int gtid = blockIdx.x * blockDim.x + threadIdx.x;
    int w    = gtid >> 6;          // edge
    int half = (gtid >> 5) & 1;    // d-half: 0 -> d in [0,32), 1 -> [32,64)
    int lane = gtid & 31;          // k
    if (w >= EPASS) return;
    int u = psrc[w];
    int v = pdst[w];

    // packed h for this half: lanes 0..15 hold pair j = (h[half*32+2j], +1);
    // lanes 16..31 mirror lanes 0..15 (shfl sources are always < 16).
    float2 f_i = *(const float2*)(hin  + (size_t)v * DIM + half * 32 + 2 * (lane & 15));
    float2 f_o = *(const float2*)(hout + (size_t)v * DIM + half * 32 + 2 * (lane & 15));
    __half2 phi = __floats2half2_rn(f_i.x, f_i.y);
    __half2 pho = __floats2half2_rn(f_o.x, f_o.y);
    unsigned phiu = *(unsigned*)&phi;
    unsigned phou = *(unsigned*)&pho;

    const float4* ev4 = (const float4*)(ek + (size_t)u * EN) + (half * 4) * 32 + lane;

    float mi = 0.f, mo = 0.f;
#pragma unroll
    for (int c = 0; c < 4; c++) {               // local chunk; global d chunk = 4*half+c
        float4 evc = ev4[c * 32];               // coalesced across lanes
        const __half2* ep = (const __half2*)&evc;  // 4 half2: d pairs
        __half2 acci, acco;
#pragma unroll
        for (int tt = 0; tt < 4; tt++) {
            unsigned hiu = __shfl_sync(0xffffffffu, phiu, 4 * c + tt);
            unsigned hou = __shfl_sync(0xffffffffu, phou, 4 * c + tt);
            __half2 hih = *(__half2*)&hiu;
            __half2 hoh = *(__half2*)&hou;
            if (tt == 0) { acci = __hmul2(ep[0], hih); acco = __hmul2(ep[0], hoh); }
            else         { acci = __hfma2(ep[tt], hih, acci);
                           acco = __hfma2(ep[tt], hoh, acco); }
        }
        float2 ai = __half22float2(acci);
        float2 ao = __half22float2(acco);
        mi += ai.x + ai.y;
        mo += ao.x + ao.y;
    }

    red_add_f(min_  + (size_t)v * 32 + lane, mi);
    red_add_f(mout_ + (size_t)v * 32 + lane, mo);
}

// ---------------------------------------------------------------------------
// K4: gather channel -> router into d_out. 8 lanes per edge, float4 chunks.
__global__ void gather_kernel(const int* __restrict__ isrc, const int* __restrict__ idst,
                              const int* __restrict__ oisrc, const int* __restrict__ oidst,
                              const float* __restrict__ min_, const float* __restrict__ mout_,
                              float* __restrict__ out) {
    int gtid = blockIdx.x * blockDim.x + threadIdx.x;
    int e = gtid >> 3;
    int c = gtid & 7;
    if (e < ERC) {
        int s = isrc[e], d = idst[e];
        float4 v = *(const float4*)(min_ + (size_t)s * 32 + c * 4);
        red_add_v4(out + (size_t)d * DIM + c * 4, v);
    } else if (e < 2 * ERC) {
        int ee = e - ERC;
        int s = oisrc[ee], d = oidst[ee];
        float4 v = *(const float4*)(mout_ + (size_t)s * 32 + c * 4);
        red_add_v4(out + (size_t)d * DIM + 32 + c * 4, v);
    }
}

// ---------------------------------------------------------------------------
// K5: relu epilogue on out
__global__ void relu_kernel(float4* __restrict__ out) {
    int i = blockIdx.x * blockDim.x + threadIdx.x;
    float4 v = out[i];
    v.x = fmaxf(v.x, 0.f); v.y = fmaxf(v.y, 0.f);
    v.z = fmaxf(v.z, 0.f); v.w = fmaxf(v.w, 0.f);
    out[i] = v;
}

// ===========================================================================
extern "C" void kernel_launch(void* const* d_in, const int* in_sizes, int n_in,
                              void* d_out, int out_size) {
    const float* h_router       = (const float*)d_in[0];
    const float* h_packet       = (const float*)d_in[1];
    const float* W_p            = (const float*)d_in[2];
    const float* b_p            = (const float*)d_in[3];
    // d_in[4] = W_c, d_in[5] = b_c : dead code in reference
    const int* output_src       = (const int*)d_in[6];
    const int* output_dst       = (const int*)d_in[7];
    const int* input_inv_src    = (const int*)d_in[8];
    const int* input_inv_dst    = (const int*)d_in[9];
    const int* pass_src         = (const int*)d_in[10];
    const int* pass_dst         = (const int*)d_in[11];
    const int* input_src        = (const int*)d_in[12];
    const int* input_dst        = (const int*)d_in[13];
    const int* output_inv_src   = (const int*)d_in[14];
    const int* output_inv_dst   = (const int*)d_in[15];
    float* out = (float*)d_out;

    __half* p_e;
    float *p_hin, *p_hout, *p_min, *p_mout;
    cudaGetSymbolAddress((void**)&p_e,    g_e);
    cudaGetSymbolAddress((void**)&p_hin,  g_hin);
    cudaGetSymbolAddress((void**)&p_hout, g_hout);
    cudaGetSymbolAddress((void**)&p_min,  g_min);
    cudaGetSymbolAddress((void**)&p_mout, g_mout);

    // Fork: side stream zeroes pass/gather outputs then runs the GEMM,
    // overlapping the hin/hout zero + scatter chain on the main stream.
    cudaEventRecord(g_ss.evFork, 0);
    cudaStreamWaitEvent(g_ss.s2, g_ss.evFork, 0);
    zero_m_kernel<<<1024, 256, 0, g_ss.s2>>>((float4*)p_min, (float4*)p_mout,
                                             (float4*)out);
    {
        dim3 grid(EN / 128, NP / 128);  // (16, 128)
        gemm_e_hmma<<<grid, 256, 0, g_ss.s2>>>(h_packet, W_p, b_p, p_e);
    }
    cudaEventRecord(g_ss.evJoin, g_ss.s2);

    // Main stream: zero hin/hout, then router->channel scatters
    zero_h_kernel<<<2048, 256>>>((float4*)p_hin, (float4*)p_hout);
    scatter_h_kernel<<<(2 * ERC * 16) / 256, 256>>>(
        output_src, output_dst, input_inv_src, input_inv_dst,
        h_router, p_hin, p_hout);

    // Join: pass needs the GEMM output, zeroed m buffers, and scattered h
    cudaStreamWaitEvent(0, g_ss.evJoin, 0);

    // pass edges: 2 warps per edge (64 threads), lane = k
    pass_kernel<<<(EPASS * 64) / 256, 256>>>(pass_src, pass_dst, p_e,
                                             p_hin, p_hout, p_min, p_mout);

    // channel -> router gathers into out (8 lanes/edge, vectorized)
    gather_kernel<<<(2 * ERC * 8) / 256, 256>>>(input_src, input_dst,
                                                output_inv_src, output_inv_dst,
                                                p_min, p_mout, out);

    // relu epilogue
    relu_kernel<<<(NR * DIM) / (4 * 256), 256>>>((float4*)out);
}

// round 16
// speedup vs baseline: 1.4080x; 1.0720x over previous
#include <cuda_runtime.h>
#include <cuda_fp16.h>
#include <cstdint>
#include <cstddef>

// Problem constants (fixed by the dataset)
#define NR    16384
#define NCH   65536
#define NP    16384
#define DIM   64
#define ERC   65536
#define EPASS 65536
#define EN    2048   // D*D/2

// Device scratch (allocation-free rule: __device__ globals)
// g_e TILED layout: addr(u,k,d) = u*2048 + (d>>3)*256 + k*8 + (d&7)
//   -> lane k's chunk c (d in [8c,8c+8)) is the float4 at (u*256 + c*32 + k)
__device__ __half g_e  [(size_t)NP  * EN];   // 64 MB
__device__ float g_hin [(size_t)NCH * DIM];  // 16 MB
__device__ float g_hout[(size_t)NCH * DIM];  // 16 MB
__device__ float g_min [(size_t)NCH * 32];   // 8 MB
__device__ float g_mout[(size_t)NCH * 32];   // 8 MB

// Side stream + fork/join events, created once at load time.
struct SideStream {
    cudaStream_t s2;
    cudaEvent_t evFork, evJoin;
    SideStream() {
        cudaStreamCreate(&s2);
        cudaEventCreateWithFlags(&evFork, cudaEventDisableTiming);
        cudaEventCreateWithFlags(&evJoin, cudaEventDisableTiming);
    }
};
static SideStream g_ss;

__device__ __forceinline__ void red_add_v4(float* p, float4 v) {
    asm volatile("red.global.add.v4.f32 [%0], {%1,%2,%3,%4};"
                 :: "l"(p), "f"(v.x), "f"(v.y), "f"(v.z), "f"(v.w) : "memory");
}
__device__ __forceinline__ void red_add_f(float* p, float v) {
    asm volatile("red.global.add.f32 [%0], %1;" :: "l"(p), "f"(v) : "memory");
}
__device__ __forceinline__ uint32_t smem_u32(const void* p) {
    return (uint32_t)__cvta_generic_to_shared(p);
}

// Map a storage column n (0..2047) to its W_p row: n = c*256 + k*8 + dd,
// d = 8c + dd, W_p row = d*32 + k.
__device__ __forceinline__ int wp_row_of_col(int n) {
    int dd = n & 7;
    int k  = (n >> 3) & 31;
    int c  = n >> 8;
    return (8 * c + dd) * 32 + k;
}

// ---------------------------------------------------------------------------
// K0a (main stream): zero hin/hout
__global__ void zero_h_kernel(float4* __restrict__ hin, float4* __restrict__ hout) {
    const int n_h = (NCH * DIM) / 4;
    float4 z = make_float4(0.f, 0.f, 0.f, 0.f);
    int stride = gridDim.x * blockDim.x;
    for (int i = blockIdx.x * blockDim.x + threadIdx.x; i < n_h; i += stride) {
        hin[i] = z; hout[i] = z;
    }
}
// K0b (side stream): zero min/mout/out
__global__ void zero_m_kernel(float4* __restrict__ min_, float4* __restrict__ mout_,
                              float4* __restrict__ out) {
    const int n_m = (NCH * 32) / 4;
    const int n_o = (NR * DIM) / 4;
    float4 z = make_float4(0.f, 0.f, 0.f, 0.f);
    int stride = gridDim.x * blockDim.x;
    for (int i = blockIdx.x * blockDim.x + threadIdx.x; i < n_m; i += stride) {
        min_[i] = z; mout_[i] = z;
    }
    for (int i = blockIdx.x * blockDim.x + threadIdx.x; i < n_o; i += stride) {
        out[i] = z;
    }
}

// ---------------------------------------------------------------------------
// K1: scatter-add h rows along edges: acc[dst[e]] += h[src[e]]  (64 floats/row)
__global__ void scatter_h_kernel(const int* __restrict__ src0, const int* __restrict__ dst0,
                                 const int* __restrict__ src1, const int* __restrict__ dst1,
                                 const float* __restrict__ h,
                                 float* __restrict__ acc0, float* __restrict__ acc1) {
    int tid = blockIdx.x * blockDim.x + threadIdx.x;
    int e = tid >> 4;
    int c = tid & 15;
    const int* src; const int* dst; float* acc;
    if (e < ERC) { src = src0; dst = dst0; acc = acc0; }
    else if (e < 2 * ERC) { e -= ERC; src = src1; dst = dst1; acc = acc1; }
    else return;
    int s = src[e];
    int d = dst[e];
    float4 v = *(const float4*)(h + (size_t)s * DIM + c * 4);
    red_add_v4(acc + (size_t)d * DIM + c * 4, v);
}

// ---------------------------------------------------------------------------
// K2: e = h_packet @ W_p^T + b_p  -> TILED fp16 output (see g_e comment).
// Storage col n reads W_p row wp_row_of_col(n). HMMA m16n8k16, fp32 acc,
// 128x128 tile, 8 warps (2m x 4n), K=64 in 4 k-steps, single stage.
// Epilogue stages the fp16 tile in smem (padded stride 136) and writes
// 2048 coalesced STG.128 — eliminates the 2x DRAM sector amplification of
// scattered STG.32 stores.
__global__ void __launch_bounds__(256) gemm_e_hmma(
        const float* __restrict__ A,    // [NP, 64] h_packet
        const float* __restrict__ B,    // [2048, 64] W_p
        const float* __restrict__ bias, // [2048] b_p
        __half* __restrict__ C) {       // [NP, 2048] tiled
    __shared__ __align__(16) __half Cbuf[128 * 136];   // 34.8 KB; aliases As/Bs
    __half* As = Cbuf;          // [128][64] swizzled (first 8192 halfs)
    __half* Bs = Cbuf + 8192;   // [128][64] swizzled
    const int t  = threadIdx.x;
    const int m0 = blockIdx.y * 128;
    const int n0 = blockIdx.x * 128;

    {
        const float* G0 = A + (size_t)m0 * DIM;
#pragma unroll
        for (int i = 0; i < 4; i++) {
            int idx = i * 256 + t;      // 0..1023
            int r = idx >> 3, ch = idx & 7;
            int pch = ch ^ (r & 7);
            {
                const float4* gp = (const float4*)(G0 + (size_t)r * DIM + ch * 8);
                float4 lo = gp[0], hi = gp[1];
                __half2 h0 = __floats2half2_rn(lo.x, lo.y);
                __half2 h1 = __floats2half2_rn(lo.z, lo.w);
                __half2 h2 = __floats2half2_rn(hi.x, hi.y);
                __half2 h3 = __floats2half2_rn(hi.z, hi.w);
                uint4 v = make_uint4(*(unsigned*)&h0, *(unsigned*)&h1,
                                     *(unsigned*)&h2, *(unsigned*)&h3);
                *(uint4*)(As + r * 64 + pch * 8) = v;
            }
            {
                int brow = wp_row_of_col(n0 + r);   // permuted W_p row
                const float4* gp = (const float4*)(B + (size_t)brow * DIM + ch * 8);
                float4 lo = gp[0], hi = gp[1];
                __half2 h0 = __floats2half2_rn(lo.x, lo.y);
                __half2 h1 = __floats2half2_rn(lo.z, lo.w);
                __half2 h2 = __floats2half2_rn(hi.x, hi.y);
                __half2 h3 = __floats2half2_rn(hi.z, hi.w);
                uint4 v = make_uint4(*(unsigned*)&h0, *(unsigned*)&h1,
                                     *(unsigned*)&h2, *(unsigned*)&h3);
                *(uint4*)(Bs + r * 64 + pch * 8) = v;
            }
        }
    }
    __syncthreads();

    const int wid  = t >> 5, lane = t & 31;
    const int mbase = (wid >> 2) * 64;   // warp_m in {0,1}
    const int nbase = (wid & 3) * 32;    // warp_n in {0..3}

    float acc[4][4][4];
#pragma unroll
    for (int mt = 0; mt < 4; mt++)
#pragma unroll
        for (int nt = 0; nt < 4; nt++)
#pragma unroll
            for (int j = 0; j < 4; j++) acc[mt][nt][j] = 0.f;

#pragma unroll
    for (int ks = 0; ks < 4; ks++) {
        uint32_t a[4][4], bf[2][4];
        const int lrow = lane & 15;
        const int lch  = 2 * ks + (lane >> 4);
#pragma unroll
        for (int mt = 0; mt < 4; mt++) {
            int r = mbase + mt * 16 + lrow;
            uint32_t addr = smem_u32(As + r * 64 + (lch ^ (r & 7)) * 8);
            asm volatile("ldmatrix.sync.aligned.m8n8.x4.shared.b16 {%0,%1,%2,%3}, [%4];"
                : "=r"(a[mt][0]), "=r"(a[mt][1]), "=r"(a[mt][2]), "=r"(a[mt][3])
                : "r"(addr));
        }
#pragma unroll
        for (int np = 0; np < 2; np++) {
            int r = nbase + np * 16 + lrow;
            uint32_t addr = smem_u32(Bs + r * 64 + (lch ^ (r & 7)) * 8);
            asm volatile("ldmatrix.sync.aligned.m8n8.x4.shared.b16 {%0,%1,%2,%3}, [%4];"
                : "=r"(bf[np][0]), "=r"(bf[np][1]), "=r"(bf[np][2]), "=r"(bf[np][3])
                : "r"(addr));
        }
#pragma unroll
        for (int mt = 0; mt < 4; mt++)
#pragma unroll
            for (int nt = 0; nt < 4; nt++) {
                uint32_t b0 = bf[nt >> 1][nt & 1];
                uint32_t b1 = bf[nt >> 1][2 + (nt & 1)];
                asm volatile(
                    "mma.sync.aligned.m16n8k16.row.col.f32.f16.f16.f32 "
                    "{%0,%1,%2,%3}, {%4,%5,%6,%7}, {%8,%9}, {%0,%1,%2,%3};"
                    : "+f"(acc[mt][nt][0]), "+f"(acc[mt][nt][1]),
                      "+f"(acc[mt][nt][2]), "+f"(acc[mt][nt][3])
                    : "r"(a[mt][0]), "r"(a[mt][1]), "r"(a[mt][2]), "r"(a[mt][3]),
                      "r"(b0), "r"(b1));
            }
    }
    __syncthreads();   // all ldmatrix reads of As/Bs done before Cbuf reuse

    // stage bias-added fp16 tile into smem (padded row stride 136 halfs)
    const int row_l = lane >> 2;
    const int col_l = (lane & 3) * 2;
#pragma unroll
    for (int mt = 0; mt < 4; mt++) {
        int ml = mbase + mt * 16 + row_l;
#pragma unroll
        for (int nt = 0; nt < 4; nt++) {
            int nl = nbase + nt * 8 + col_l;
            int b0row = wp_row_of_col(n0 + nl);
            float bx = bias[b0row];
            float by = bias[b0row + 32];           // col n+1: d+1 -> row+32
            __half2 h01 = __floats2half2_rn(acc[mt][nt][0] + bx,
                                            acc[mt][nt][1] + by);
            __half2 h23 = __floats2half2_rn(acc[mt][nt][2] + bx,
                                            acc[mt][nt][3] + by);
            *(__half2*)(Cbuf + ml * 136 + nl)       = h01;
            *(__half2*)(Cbuf + (ml + 8) * 136 + nl) = h23;
        }
    }
    __syncthreads();

    // coalesced writeback: 128 rows x 256B, 16 uint4 per row
#pragma unroll
    for (int i = 0; i < 8; i++) {
        int idx = i * 256 + t;           // 0..2047
        int r = idx >> 4, ch = idx & 15;
        uint4 v = *(uint4*)(Cbuf + r * 136 + ch * 8);
        *(uint4*)(C + (size_t)(m0 + r) * EN + n0 + ch * 8) = v;
    }
}

// ---------------------------------------------------------------------------
// K3: pass edges, tiled e. One warp per edge; lane = k (0..31):
//   m_in[v,k]  = sum_d e[u,k,d] * h_in[v,d]   (same for m_out)
// Chunk c: coalesced LDG.128 at (u*256 + c*32 + lane) float4s; h broadcast
// as packed half2 via shfl; HFMA2 chunk accumulation upconverted to f32
// each 8 terms. No cross-lane reduce; scalar red per lane.
__global__ void pass_kernel(
        const int* __restrict__ psrc, const int* __restrict__ pdst,
        const __half* __restrict__ ek,
        const float* __restrict__ hin, const float* __restrict__ hout,
        float* __restrict__ min_, float* __restrict__ mout_) {
    int gtid = blockIdx.x * blockDim.x + threadIdx.x;
    int w    = gtid >> 5;
    int lane = gtid & 31;
    if (w >= EPASS) return;
    int u = psrc[w];
    int v = pdst[w];

    // packed h: lane j holds (h[2j], h[2j+1]) as half2
    float2 fi = *(const float2*)(hin  + (size_t)v * DIM + 2 * lane);
    float2 fo = *(const float2*)(hout + (size_t)v * DIM + 2 * lane);
    __half2 phi = __floats2half2_rn(fi.x, fi.y);
    __half2 pho = __floats2half2_rn(fo.x, fo.y);
    unsigned phiu = *(unsigned*)&phi;
    unsigned phou = *(unsigned*)&pho;

    const float4* ev4 = (const float4*)(ek + (size_t)u * EN) + lane;

    float mi = 0.f, mo = 0.f;
#pragma unroll
    for (int c = 0; c < 8; c++) {               // d chunk = [8c, 8c+8)
        float4 evc = ev4[c * 32];               // coalesced across lanes
        const __half2* ep = (const __half2*)&evc;  // 4 half2: d pairs
        __half2 acci, acco;
#pragma unroll
        for (int tt = 0; tt < 4; tt++) {
            unsigned hiu = __shfl_sync(0xffffffffu, phiu, 4 * c + tt);
            unsigned hou = __shfl_sync(0xffffffffu, phou, 4 * c + tt);
            __half2 hih = *(__half2*)&hiu;
            __half2 hoh = *(__half2*)&hou;
            if (tt == 0) { acci = __hmul2(ep[0], hih); acco = __hmul2(ep[0], hoh); }
            else         { acci = __hfma2(ep[tt], hih, acci);
                           acco = __hfma2(ep[tt], hoh, acco); }
        }
        float2 ai = __half22float2(acci);
        float2 ao = __half22float2(acco);
        mi += ai.x + ai.y;
        mo += ao.x + ao.y;
    }

    red_add_f(min_  + (size_t)v * 32 + lane, mi);
    red_add_f(mout_ + (size_t)v * 32 + lane, mo);
}

// ---------------------------------------------------------------------------
// K4: gather channel -> router into d_out. 8 lanes per edge, float4 chunks.
__global__ void gather_kernel(const int* __restrict__ isrc, const int* __restrict__ idst,
                              const int* __restrict__ oisrc, const int* __restrict__ oidst,
                              const float* __restrict__ min_, const float* __restrict__ mout_,
                              float* __restrict__ out) {
    int gtid = blockIdx.x * blockDim.x + threadIdx.x;
    int e = gtid >> 3;
    int c = gtid & 7;
    if (e < ERC) {
        int s = isrc[e], d = idst[e];
        float4 v = *(const float4*)(min_ + (size_t)s * 32 + c * 4);
        red_add_v4(out + (size_t)d * DIM + c * 4, v);
    } else if (e < 2 * ERC) {
        int ee = e - ERC;
        int s = oisrc[ee], d = oidst[ee];
        float4 v = *(const float4*)(mout_ + (size_t)s * 32 + c * 4);
        red_add_v4(out + (size_t)d * DIM + 32 + c * 4, v);
    }
}

// ---------------------------------------------------------------------------
// K5: relu epilogue on out
__global__ void relu_kernel(float4* __restrict__ out) {
    int i = blockIdx.x * blockDim.x + threadIdx.x;
    float4 v = out[i];
    v.x = fmaxf(v.x, 0.f); v.y = fmaxf(v.y, 0.f);
    v.z = fmaxf(v.z, 0.f); v.w = fmaxf(v.w, 0.f);
    out[i] = v;
}

// ===========================================================================
extern "C" void kernel_launch(void* const* d_in, const int* in_sizes, int n_in,
                              void* d_out, int out_size) {
    const float* h_router       = (const float*)d_in[0];
    const float* h_packet       = (const float*)d_in[1];
    const float* W_p            = (const float*)d_in[2];
    const float* b_p            = (const float*)d_in[3];
    // d_in[4] = W_c, d_in[5] = b_c : dead code in reference
    const int* output_src       = (const int*)d_in[6];
    const int* output_dst       = (const int*)d_in[7];
    const int* input_inv_src    = (const int*)d_in[8];
    const int* input_inv_dst    = (const int*)d_in[9];
    const int* pass_src         = (const int*)d_in[10];
    const int* pass_dst         = (const int*)d_in[11];
    const int* input_src        = (const int*)d_in[12];
    const int* input_dst        = (const int*)d_in[13];
    const int* output_inv_src   = (const int*)d_in[14];
    const int* output_inv_dst   = (const int*)d_in[15];
    float* out = (float*)d_out;

    __half* p_e;
    float *p_hin, *p_hout, *p_min, *p_mout;
    cudaGetSymbolAddress((void**)&p_e,    g_e);
    cudaGetSymbolAddress((void**)&p_hin,  g_hin);
    cudaGetSymbolAddress((void**)&p_hout, g_hout);
    cudaGetSymbolAddress((void**)&p_min,  g_min);
    cudaGetSymbolAddress((void**)&p_mout, g_mout);

    // Fork: side stream zeroes pass/gather outputs then runs the GEMM,
    // overlapping the hin/hout zero + scatter chain on the main stream.
    cudaEventRecord(g_ss.evFork, 0);
    cudaStreamWaitEvent(g_ss.s2, g_ss.evFork, 0);
    zero_m_kernel<<<1024, 256, 0, g_ss.s2>>>((float4*)p_min, (float4*)p_mout,
                                             (float4*)out);
    {
        dim3 grid(EN / 128, NP / 128);  // (16, 128)
        gemm_e_hmma<<<grid, 256, 0, g_ss.s2>>>(h_packet, W_p, b_p, p_e);
    }
    cudaEventRecord(g_ss.evJoin, g_ss.s2);

    // Main stream: zero hin/hout, then router->channel scatters
    zero_h_kernel<<<2048, 256>>>((float4*)p_hin, (float4*)p_hout);
    scatter_h_kernel<<<(2 * ERC * 16) / 256, 256>>>(
        output_src, output_dst, input_inv_src, input_inv_dst,
        h_router, p_hin, p_hout);

    // Join: pass needs the GEMM output, zeroed m buffers, and scattered h
    cudaStreamWaitEvent(0, g_ss.evJoin, 0);

    // pass edges: warp per edge, lane = k
    pass_kernel<<<(EPASS * 32) / 256, 256>>>(pass_src, pass_dst, p_e,
                                             p_hin, p_hout, p_min, p_mout);

    // channel -> router gathers into out (8 lanes/edge, vectorized)
    gather_kernel<<<(2 * ERC * 8) / 256, 256>>>(input_src, input_dst,
                                                output_inv_src, output_inv_dst,
                                                p_min, p_mout, out);

    // relu epilogue
    relu_kernel<<<(NR * DIM) / (4 * 256), 256>>>((float4*)out);
}